// round 4
// baseline (speedup 1.0000x reference)
#include <cuda_runtime.h>
#include <cstdint>

#define H 128
typedef unsigned long long ull;

// Node-level normalized feature scratch: 50000 x 128 fp32 = 25.6 MB (L2-resident)
#define MAX_N 50048
__device__ float g_zn[(size_t)MAX_N * H];

// ---------------------------------------------------------------------------
// Packed fp32x2 helpers (Blackwell FFMA2 path)
// ---------------------------------------------------------------------------
__device__ __forceinline__ void ffma2(ull &d, ull a, ull b) {
    asm("fma.rn.f32x2 %0, %1, %2, %0;" : "+l"(d) : "l"(a), "l"(b));
}
__device__ __forceinline__ ull pack2(float lo, float hi) {
    ull r; asm("mov.b64 %0, {%1, %2};" : "=l"(r) : "f"(lo), "f"(hi)); return r;
}
__device__ __forceinline__ float2 unpack2(ull p) {
    float2 f; asm("mov.b64 {%0, %1}, %2;" : "=f"(f.x), "=f"(f.y) : "l"(p)); return f;
}

// ---------------------------------------------------------------------------
// Kernel A: per-node MLP (Linear->ELU->Linear) + L2-normalize (with eps clamp)
//   emb [N,128] -> g_zn [N,128],  zn = z / max(||z||, 1e-8)
// Persistent blocks, 256 threads, smem = W1^T (64K) + W2^T (64K) + act (64K)
// Each warp processes 8 rows; lane j owns output cols 4j..4j+3.
// Activations stored as duplicated (v,v) 64-bit pairs -> FFMA2 with no MOVs.
// ---------------------------------------------------------------------------
#define TILE_ROWS 64          // 8 warps * 8 rows
#define SMEM_A (2 * H * H * 4 + 8 * 8 * H * 8)   // 196608 bytes

__global__ __launch_bounds__(256, 1)
void mlp_norm_kernel(const float* __restrict__ emb,
                     const float* __restrict__ W1, const float* __restrict__ b1,
                     const float* __restrict__ W2, const float* __restrict__ b2,
                     int N, int n_tiles)
{
    extern __shared__ float smem[];
    float* W1t = smem;                 // [k][j] k-major, 128x128
    float* W2t = smem + H * H;
    ull*   xs2 = (ull*)(smem + 2 * H * H);  // [8 warps][8 rows][128] dup pairs

    const int tid  = threadIdx.x;
    const int warp = tid >> 5;
    const int lane = tid & 31;

    // Transpose-load both weight matrices into smem (once per block)
    for (int idx = tid; idx < H * H; idx += blockDim.x) {
        int j = idx >> 7, k = idx & (H - 1);     // W[j][k]
        W1t[k * H + j] = W1[idx];
        W2t[k * H + j] = W2[idx];
    }
    __syncthreads();

    ull* myx = xs2 + (size_t)warp * 8 * H;       // this warp's 8 activation rows

    // Bias pairs for my columns
    float4 bv1 = ((const float4*)b1)[lane];
    float4 bv2 = ((const float4*)b2)[lane];
    const ull b1p0 = pack2(bv1.x, bv1.y), b1p1 = pack2(bv1.z, bv1.w);
    const ull b2p0 = pack2(bv2.x, bv2.y), b2p1 = pack2(bv2.z, bv2.w);

    for (int tile = blockIdx.x; tile < n_tiles; tile += gridDim.x) {
        const int row0 = tile * TILE_ROWS + warp * 8;

        __syncwarp();   // protect myx against previous iteration's readers
        // Load 8 input rows, store duplicated pairs
        #pragma unroll
        for (int r = 0; r < 8; r++) {
            int row = row0 + r;
            float4 v = make_float4(0.f, 0.f, 0.f, 0.f);
            if (row < N) v = ((const float4*)(emb + (size_t)row * H))[lane];
            ull* dst = myx + r * H + lane * 4;
            dst[0] = pack2(v.x, v.x); dst[1] = pack2(v.y, v.y);
            dst[2] = pack2(v.z, v.z); dst[3] = pack2(v.w, v.w);
        }
        __syncwarp();

        ull acc[8][2];

        // ---- Layer 1: h = x @ W1^T + b1 ----
        #pragma unroll
        for (int r = 0; r < 8; r++) { acc[r][0] = b1p0; acc[r][1] = b1p1; }
        {
            const ulonglong2* wp = (const ulonglong2*)W1t;
            #pragma unroll 4
            for (int k = 0; k < H; k++) {
                ulonglong2 w = wp[k * (H / 4) + lane];   // W1t[k][4*lane..4*lane+3]
                #pragma unroll
                for (int r = 0; r < 8; r++) {
                    ull xv = myx[r * H + k];
                    ffma2(acc[r][0], xv, w.x);
                    ffma2(acc[r][1], xv, w.y);
                }
            }
        }
        __syncwarp();

        // ---- ELU, write back duplicated ----
        #pragma unroll
        for (int r = 0; r < 8; r++) {
            float2 a = unpack2(acc[r][0]);
            float2 b = unpack2(acc[r][1]);
            float h0 = a.x > 0.f ? a.x : expm1f(a.x);
            float h1 = a.y > 0.f ? a.y : expm1f(a.y);
            float h2 = b.x > 0.f ? b.x : expm1f(b.x);
            float h3 = b.y > 0.f ? b.y : expm1f(b.y);
            ull* dst = myx + r * H + lane * 4;
            dst[0] = pack2(h0, h0); dst[1] = pack2(h1, h1);
            dst[2] = pack2(h2, h2); dst[3] = pack2(h3, h3);
        }
        __syncwarp();

        // ---- Layer 2: z = h @ W2^T + b2 ----
        #pragma unroll
        for (int r = 0; r < 8; r++) { acc[r][0] = b2p0; acc[r][1] = b2p1; }
        {
            const ulonglong2* wp = (const ulonglong2*)W2t;
            #pragma unroll 4
            for (int k = 0; k < H; k++) {
                ulonglong2 w = wp[k * (H / 4) + lane];
                #pragma unroll
                for (int r = 0; r < 8; r++) {
                    ull xv = myx[r * H + k];
                    ffma2(acc[r][0], xv, w.x);
                    ffma2(acc[r][1], xv, w.y);
                }
            }
        }

        // ---- Row norms (warp-local reduce) + normalized store ----
        #pragma unroll
        for (int r = 0; r < 8; r++) {
            float2 a = unpack2(acc[r][0]);
            float2 b = unpack2(acc[r][1]);
            float s = a.x * a.x + a.y * a.y + b.x * b.x + b.y * b.y;
            #pragma unroll
            for (int off = 16; off; off >>= 1)
                s += __shfl_xor_sync(0xFFFFFFFFu, s, off);
            float inv = 1.0f / fmaxf(sqrtf(s), 1e-8f);
            int row = row0 + r;
            if (row < N) {
                float4 o = make_float4(a.x * inv, a.y * inv, b.x * inv, b.y * inv);
                ((float4*)(g_zn + (size_t)row * H))[lane] = o;
            }
        }
    }
}

// ---------------------------------------------------------------------------
// Kernel B: per-edge cosine = dot(zn[col], zn[row]); warp per edge.
// zn working set (25.6 MB) is L2-resident -> gathers are L2 hits.
// edge_index read as int32. Indices clamped defensively: if the dtype theory
// is wrong this yields a wrong answer + profile instead of a blind crash.
// ---------------------------------------------------------------------------
__global__ __launch_bounds__(256)
void edge_cos_kernel(const int* __restrict__ ei,
                     float* __restrict__ out, int E, int N)
{
    int wg   = (blockIdx.x * blockDim.x + threadIdx.x) >> 5;
    int lane = threadIdx.x & 31;
    if (wg >= E) return;

    int c = __ldg(ei + wg);
    int r = __ldg(ei + E + wg);
    c = min(max(c, 0), N - 1);
    r = min(max(r, 0), N - 1);

    const float4* p1 = (const float4*)(g_zn + (size_t)c * H);
    const float4* p2 = (const float4*)(g_zn + (size_t)r * H);
    float4 a = p1[lane];
    float4 b = p2[lane];
    float s = a.x * b.x + a.y * b.y + a.z * b.z + a.w * b.w;
    #pragma unroll
    for (int off = 16; off; off >>= 1)
        s += __shfl_xor_sync(0xFFFFFFFFu, s, off);
    if (lane == 0) out[wg] = s;
}

// ---------------------------------------------------------------------------
extern "C" void kernel_launch(void* const* d_in, const int* in_sizes, int n_in,
                              void* d_out, int out_size)
{
    const float* emb = (const float*)d_in[0];
    const int*   ei  = (const int*)d_in[1];
    const float* W1  = (const float*)d_in[2];
    const float* b1  = (const float*)d_in[3];
    const float* W2  = (const float*)d_in[4];
    const float* b2  = (const float*)d_in[5];
    float* out = (float*)d_out;

    int N = in_sizes[0] / H;
    int E = in_sizes[1] / 2;
    int n_tiles = (N + TILE_ROWS - 1) / TILE_ROWS;

    cudaFuncSetAttribute(mlp_norm_kernel,
                         cudaFuncAttributeMaxDynamicSharedMemorySize, SMEM_A);

    int gridA = n_tiles < 148 ? n_tiles : 148;
    mlp_norm_kernel<<<gridA, 256, SMEM_A>>>(emb, W1, b1, W2, b2, N, n_tiles);

    int warps  = E;
    int blocks = (warps + 7) / 8;     // 8 warps (256 threads) per block
    edge_cos_kernel<<<blocks, 256>>>(ei, out, E, N);
}

// round 5
// speedup vs baseline: 1.2951x; 1.2951x over previous
#include <cuda_runtime.h>
#include <cstdint>

#define H 128
typedef unsigned long long ull;

// Node-level normalized feature scratch: 50000 x 128 fp32 = 25.6 MB (L2-resident)
#define MAX_N 50048
__device__ float g_zn[(size_t)MAX_N * H];

// ---------------------------------------------------------------------------
// Packed fp32x2 helpers (Blackwell FFMA2 path)
// ---------------------------------------------------------------------------
__device__ __forceinline__ void ffma2(ull &d, ull a, ull b) {
    asm("fma.rn.f32x2 %0, %1, %2, %0;" : "+l"(d) : "l"(a), "l"(b));
}
__device__ __forceinline__ ull pack2(float lo, float hi) {
    ull r; asm("mov.b64 %0, {%1, %2};" : "=l"(r) : "f"(lo), "f"(hi)); return r;
}
__device__ __forceinline__ float2 unpack2(ull p) {
    float2 f; asm("mov.b64 {%0, %1}, %2;" : "=f"(f.x), "=f"(f.y) : "l"(p)); return f;
}

// ---------------------------------------------------------------------------
// Kernel A: per-node MLP (Linear->ELU->Linear) + L2-normalize.
// K-packed FFMA2: acc[r][j] = (even-k partial, odd-k partial); activations are
// read as NATURAL contiguous (x[2k],x[2k+1]) pairs -> 1 LDS.128 broadcast per
// row per 4 k's (was 8 LDS.64 dup broadcasts per 1 k). Crossbar demand drops
// below FMA-issue demand -> FMA-bound.
// smem: W1p 64K + W2p 64K (pair-of-k packed, [k/2][j]) + act 16K = 144 KB.
// 8 warps x 8 rows; lane owns output cols 4*lane..4*lane+3.
// ---------------------------------------------------------------------------
#define TILE_ROWS 64
#define SMEM_A (2 * (H/2) * H * 8 + 8 * 8 * H * 4)   // 147456 bytes

__global__ __launch_bounds__(256, 1)
void mlp_norm_kernel(const float* __restrict__ emb,
                     const float* __restrict__ W1, const float* __restrict__ b1,
                     const float* __restrict__ W2, const float* __restrict__ b2,
                     int N, int n_tiles)
{
    extern __shared__ char smem_raw[];
    ull*   W1p = (ull*)smem_raw;                       // [64][128] (W[j][2kp],W[j][2kp+1])
    ull*   W2p = W1p + (H/2) * H;
    float* xs  = (float*)(W2p + (H/2) * H);            // [8 warps][8 rows][128]

    const int tid  = threadIdx.x;
    const int warp = tid >> 5;
    const int lane = tid & 31;

    // Pack both weight matrices into k-pair layout (coalesced float2 loads)
    for (int idx = tid; idx < (H/2) * H; idx += blockDim.x) {
        int kp = idx & (H/2 - 1);         // 0..63
        int j  = idx >> 6;                // 0..127
        float2 v1 = *(const float2*)(W1 + j * H + 2 * kp);
        float2 v2 = *(const float2*)(W2 + j * H + 2 * kp);
        W1p[kp * H + j] = pack2(v1.x, v1.y);
        W2p[kp * H + j] = pack2(v2.x, v2.y);
    }
    __syncthreads();

    float* myx = xs + warp * 8 * H;      // this warp's 8 activation rows

    // Bias for my 4 columns (added to lo half; hi half starts at 0)
    float4 bv1 = ((const float4*)b1)[lane];
    float4 bv2 = ((const float4*)b2)[lane];

    for (int tile = blockIdx.x; tile < n_tiles; tile += gridDim.x) {
        const int row0 = tile * TILE_ROWS + warp * 8;

        __syncwarp();
        // Load 8 input rows (natural layout)
        #pragma unroll
        for (int r = 0; r < 8; r++) {
            int row = row0 + r;
            float4 v = make_float4(0.f, 0.f, 0.f, 0.f);
            if (row < N) v = ((const float4*)(emb + (size_t)row * H))[lane];
            ((float4*)(myx + r * H))[lane] = v;
        }
        __syncwarp();

        ull acc[8][4];

        // ---- Layer 1: h = x @ W1^T + b1 ----
        #pragma unroll
        for (int r = 0; r < 8; r++) {
            acc[r][0] = pack2(bv1.x, 0.f); acc[r][1] = pack2(bv1.y, 0.f);
            acc[r][2] = pack2(bv1.z, 0.f); acc[r][3] = pack2(bv1.w, 0.f);
        }
        #pragma unroll 4
        for (int kq = 0; kq < H/4; kq++) {             // 4 k-values per iter
            const ulonglong2* wA = (const ulonglong2*)(W1p + (2*kq)   * H + 4*lane);
            const ulonglong2* wB = (const ulonglong2*)(W1p + (2*kq+1) * H + 4*lane);
            ulonglong2 wA0 = wA[0], wA1 = wA[1];       // cols 4l..4l+3, k-pair 2kq
            ulonglong2 wB0 = wB[0], wB1 = wB[1];       // cols 4l..4l+3, k-pair 2kq+1
            #pragma unroll
            for (int r = 0; r < 8; r++) {
                ulonglong2 x2 = ((const ulonglong2*)(myx + r * H))[kq];  // broadcast
                ffma2(acc[r][0], x2.x, wA0.x); ffma2(acc[r][1], x2.x, wA0.y);
                ffma2(acc[r][2], x2.x, wA1.x); ffma2(acc[r][3], x2.x, wA1.y);
                ffma2(acc[r][0], x2.y, wB0.x); ffma2(acc[r][1], x2.y, wB0.y);
                ffma2(acc[r][2], x2.y, wB1.x); ffma2(acc[r][3], x2.y, wB1.y);
            }
        }
        __syncwarp();

        // ---- ELU (lo+hi fold), write back natural layout ----
        #pragma unroll
        for (int r = 0; r < 8; r++) {
            float2 a0 = unpack2(acc[r][0]), a1 = unpack2(acc[r][1]);
            float2 a2 = unpack2(acc[r][2]), a3 = unpack2(acc[r][3]);
            float z0 = a0.x + a0.y, z1 = a1.x + a1.y;
            float z2 = a2.x + a2.y, z3 = a3.x + a3.y;
            float4 hv;
            hv.x = z0 > 0.f ? z0 : expm1f(z0);
            hv.y = z1 > 0.f ? z1 : expm1f(z1);
            hv.z = z2 > 0.f ? z2 : expm1f(z2);
            hv.w = z3 > 0.f ? z3 : expm1f(z3);
            ((float4*)(myx + r * H))[lane] = hv;
        }
        __syncwarp();

        // ---- Layer 2: z = h @ W2^T + b2 ----
        #pragma unroll
        for (int r = 0; r < 8; r++) {
            acc[r][0] = pack2(bv2.x, 0.f); acc[r][1] = pack2(bv2.y, 0.f);
            acc[r][2] = pack2(bv2.z, 0.f); acc[r][3] = pack2(bv2.w, 0.f);
        }
        #pragma unroll 4
        for (int kq = 0; kq < H/4; kq++) {
            const ulonglong2* wA = (const ulonglong2*)(W2p + (2*kq)   * H + 4*lane);
            const ulonglong2* wB = (const ulonglong2*)(W2p + (2*kq+1) * H + 4*lane);
            ulonglong2 wA0 = wA[0], wA1 = wA[1];
            ulonglong2 wB0 = wB[0], wB1 = wB[1];
            #pragma unroll
            for (int r = 0; r < 8; r++) {
                ulonglong2 x2 = ((const ulonglong2*)(myx + r * H))[kq];
                ffma2(acc[r][0], x2.x, wA0.x); ffma2(acc[r][1], x2.x, wA0.y);
                ffma2(acc[r][2], x2.x, wA1.x); ffma2(acc[r][3], x2.x, wA1.y);
                ffma2(acc[r][0], x2.y, wB0.x); ffma2(acc[r][1], x2.y, wB0.y);
                ffma2(acc[r][2], x2.y, wB1.x); ffma2(acc[r][3], x2.y, wB1.y);
            }
        }

        // ---- Row norms + normalized store ----
        #pragma unroll
        for (int r = 0; r < 8; r++) {
            float2 a0 = unpack2(acc[r][0]), a1 = unpack2(acc[r][1]);
            float2 a2 = unpack2(acc[r][2]), a3 = unpack2(acc[r][3]);
            float z0 = a0.x + a0.y, z1 = a1.x + a1.y;
            float z2 = a2.x + a2.y, z3 = a3.x + a3.y;
            float s = z0*z0 + z1*z1 + z2*z2 + z3*z3;
            #pragma unroll
            for (int off = 16; off; off >>= 1)
                s += __shfl_xor_sync(0xFFFFFFFFu, s, off);
            float inv = 1.0f / fmaxf(sqrtf(s), 1e-8f);
            int row = row0 + r;
            if (row < N) {
                float4 o = make_float4(z0 * inv, z1 * inv, z2 * inv, z3 * inv);
                ((float4*)(g_zn + (size_t)row * H))[lane] = o;
            }
        }
    }
}

// ---------------------------------------------------------------------------
// Kernel B: per-edge cosine. 4 edges/warp, 8 lanes/edge -> 8 independent
// LDG.128 front-batched per warp (latency hiding), 16 in-thread FMAs/lane,
// 3-level shuffle tree (was 5). zn is L2-resident.
// ---------------------------------------------------------------------------
__global__ __launch_bounds__(256)
void edge_cos_kernel(const int* __restrict__ ei,
                     float* __restrict__ out, int E, int N)
{
    int warp_id = (blockIdx.x * blockDim.x + threadIdx.x) >> 5;
    int lane = threadIdx.x & 31;
    int sub  = lane & 7;       // lane within edge group
    int eg   = lane >> 3;      // edge within warp
    int e = warp_id * 4 + eg;
    bool valid = e < E;
    int ec = valid ? __ldg(ei + e) : 0;
    int er = valid ? __ldg(ei + E + e) : 0;
    ec = min(max(ec, 0), N - 1);
    er = min(max(er, 0), N - 1);

    const float4* pa = (const float4*)(g_zn + (size_t)ec * H);
    const float4* pb = (const float4*)(g_zn + (size_t)er * H);

    float4 a0 = pa[sub],      b0 = pb[sub];
    float4 a1 = pa[sub + 8],  b1 = pb[sub + 8];
    float4 a2 = pa[sub + 16], b2 = pb[sub + 16];
    float4 a3 = pa[sub + 24], b3 = pb[sub + 24];

    float s0 = a0.x*b0.x + a0.y*b0.y + a0.z*b0.z + a0.w*b0.w;
    float s1 = a1.x*b1.x + a1.y*b1.y + a1.z*b1.z + a1.w*b1.w;
    s0 += a2.x*b2.x + a2.y*b2.y + a2.z*b2.z + a2.w*b2.w;
    s1 += a3.x*b3.x + a3.y*b3.y + a3.z*b3.z + a3.w*b3.w;
    float s = s0 + s1;

    s += __shfl_xor_sync(0xFFFFFFFFu, s, 4);
    s += __shfl_xor_sync(0xFFFFFFFFu, s, 2);
    s += __shfl_xor_sync(0xFFFFFFFFu, s, 1);
    if (sub == 0 && valid) out[e] = s;
}

// ---------------------------------------------------------------------------
extern "C" void kernel_launch(void* const* d_in, const int* in_sizes, int n_in,
                              void* d_out, int out_size)
{
    const float* emb = (const float*)d_in[0];
    const int*   ei  = (const int*)d_in[1];
    const float* W1  = (const float*)d_in[2];
    const float* b1  = (const float*)d_in[3];
    const float* W2  = (const float*)d_in[4];
    const float* b2  = (const float*)d_in[5];
    float* out = (float*)d_out;

    int N = in_sizes[0] / H;
    int E = in_sizes[1] / 2;
    int n_tiles = (N + TILE_ROWS - 1) / TILE_ROWS;

    cudaFuncSetAttribute(mlp_norm_kernel,
                         cudaFuncAttributeMaxDynamicSharedMemorySize, SMEM_A);

    int gridA = n_tiles < 148 ? n_tiles : 148;
    mlp_norm_kernel<<<gridA, 256, SMEM_A>>>(emb, W1, b1, W2, b2, N, n_tiles);

    int warps  = (E + 3) / 4;              // 4 edges per warp
    int blocks = (warps + 7) / 8;          // 8 warps per block
    edge_cos_kernel<<<blocks, 256>>>(ei, out, E, N);
}